// round 11
// baseline (speedup 1.0000x reference)
#include <cuda_runtime.h>
#include <cuda_bf16.h>
#include <cstdint>

// ---------------------------------------------------------------------------
// Model_70222715289880: bilinear score -> top-k(10/64) -> gather of 10 tensors
// B=8, K=64, TOPK=10, N_R=4, L_R=128, H=512, D=128, D2=640.
//
// R11: fuse q+score into one 48-block kernel. Score blocks prefetch their
// 169KB a_s_r burst BEFORE spin-waiting on the q-done flag, hiding score's
// load behind q's compute. q uses a 2-group cp.async split (d<320 / d>=320)
// to overlap its own load drain with the first half of the chain.
// Gather h_r path: 8 float4 per thread (MLP 8).
// FP summation order is BIT-IDENTICAL to all passing rounds (R2-R10).
// ---------------------------------------------------------------------------

#define Bq   8
#define Kk   64
#define TOPK 10
#define D2   640

#define OFF_SCORES   0
#define OFF_RATINGS  21238160
#define OFF_IDX      21248480

// vec4 (float4) offsets of gathered segments in dst
#define V4_SR    20u
#define V4_HR    40980u
#define V4_RA    5283860u
#define V4_RO    5294100u
#define V4_MASK  5304340u
#define V4_RB    5304420u
#define V4_RM    5306980u
#define V4_RE    5309560u

// small-gather compacted ranges (f4 units), h_r excluded
#define SM_SR_END  40960u
#define SM_RA_END  51200u
#define SM_RO_END  61440u
#define SM_MK_END  61520u
#define SM_RB_END  64080u
#define SM_RM_END  66640u
#define SM_TOTAL   69200u

#define HR_BLOCKS  2560    // 80 rows * 32 chunks (2048 f4 each)
#define SM_BLOCKS  128

__device__ int      g_topk_idx[Bq * TOPK];
__device__ float    g_q[Bq * D2];
__device__ unsigned g_qdone;    // zero-init; reset at end of every invocation
__device__ unsigned g_sdone;

// -------------------------------- cp.async --------------------------------
__device__ __forceinline__ void cpa16(uint32_t dst_smem, const void* src) {
    asm volatile("cp.async.cg.shared.global [%0], [%1], 16;"
                 :: "r"(dst_smem), "l"(src));
}
#define CPA_COMMIT()  asm volatile("cp.async.commit_group;")
#define CPA_WAIT(N)   asm volatile("cp.async.wait_group %0;" :: "n"(N) : "memory")

__device__ __forceinline__ uint32_t smem_u32(const void* p) {
    return (uint32_t)__cvta_generic_to_shared(p);
}

// ---------------------------------------------------------------------------
// XLA's tanh (Eigen generic_fast_tanh_float as emitted by elemental_ir_emitter)
// ---------------------------------------------------------------------------
__device__ __forceinline__ float xla_tanhf(float x)
{
    const float kClamp = 7.90531110763549805f;
    float xc = fmaxf(-kClamp, fminf(x, kClamp));
    float x2 = xc * xc;

    float p = fmaf(x2, -2.76076847742355e-16f, 2.00018790482477e-13f);
    p = fmaf(x2, p, -8.60467152213735e-11f);
    p = fmaf(x2, p,  5.12229709037114e-08f);
    p = fmaf(x2, p,  1.48572235717979e-05f);
    p = fmaf(x2, p,  6.37261928875436e-04f);
    p = fmaf(x2, p,  4.89352455891786e-03f);
    p = xc * p;

    float q = fmaf(x2, 1.19825839466702e-06f, 1.18534705686654e-04f);
    q = fmaf(x2, q, 2.26843463243900e-03f);
    q = fmaf(x2, q, 4.89352518554385e-03f);

    float r = p / q;
    return (fabsf(x) < 0.0004f) ? x : r;
}

// total-order key on float (ascending)
__device__ __forceinline__ unsigned ord_f32(float f)
{
    int i = __float_as_int(f);
    return (i < 0) ? ~(unsigned)i : ((unsigned)i | 0x80000000u);
}

// ---------------------------------------------------------------------------
// Fused kernel: 48 blocks x 256 threads.
//  blocks 0..39  (Q): block (es=bid%20, bg=bid/20); e-slice [32es,+32),
//      batches [4bg,+4). All 8 warps load; warps 0..3 run the chains
//      (warp w -> b = 4bg+w, lane l -> e). 2-group cp.async split.
//  blocks 40..47 (S): b = bid-40. Prefetch whole a_s_r[b] (64x640, rows
//      padded to 652) BEFORE spinning on g_qdone; then R2-identical dot
//      (4 thr/k, stride-4 chains, shfl 1,2) + warp top-k; self-resets flags.
// Dynamic smem = max(102400, 169472) = 169472 B.
// ---------------------------------------------------------------------------
#define SROW2    652
#define QS_SMEM  ((D2 + Kk * SROW2) * 4)     // 169,472 B (score side, larger)

__global__ __launch_bounds__(256) void qs_kernel(
    const float* __restrict__ a_s_q,
    const float* __restrict__ W,
    const float* __restrict__ a_s_r,
    const int*   __restrict__ ratings,
    float* __restrict__ out)
{
    extern __shared__ float dynm[];
    const int tid = threadIdx.x;

    if (blockIdx.x < 40) {
        // =================== Q part ===================
        float* aq = dynm;                 // [8][640]
        float* wt = dynm + 8 * D2;        // [640][32] row stride 32 floats

        const int w   = tid >> 5;
        const int l   = tid & 31;
        const int es  = blockIdx.x % 20;
        const int bg  = blockIdx.x / 20;
        const int e0  = es * 32;

        const uint32_t aq_s = smem_u32(aq);
        const uint32_t wt_s = smem_u32(wt);

        // group A: a_s_q (1280 f4, 5/thread) + W rows 0..319 (2560 f4, 10/thread)
        #pragma unroll
        for (int r = 0; r < 5; ++r) {
            const int j = tid + 256 * r;
            cpa16(aq_s + (uint32_t)j * 16u, a_s_q + j * 4);
        }
        #pragma unroll
        for (int r = 0; r < 10; ++r) {
            const int j   = tid + 256 * r;          // 0..2559
            const int row = j >> 3;                 // 0..319
            const int c   = j & 7;
            cpa16(wt_s + (uint32_t)j * 16u, W + row * D2 + e0 + c * 4);
        }
        CPA_COMMIT();
        // group B: W rows 320..639
        #pragma unroll
        for (int r = 10; r < 20; ++r) {
            const int j   = tid + 256 * r;          // 2560..5119
            const int row = j >> 3;                 // 320..639
            const int c   = j & 7;
            cpa16(wt_s + (uint32_t)j * 16u, W + row * D2 + e0 + c * 4);
        }
        CPA_COMMIT();

        CPA_WAIT(1);
        __syncthreads();

        const int b = bg * 4 + w;        // valid for w<4
        float s = 0.f;
        if (w < 4) {
            const float* aqb = aq + b * D2;
            const float* wl  = wt + l;
            #pragma unroll 16
            for (int d = 0; d < 320; ++d)
                s = fmaf(aqb[d], wl[d * 32], s);
        }
        CPA_WAIT(0);
        __syncthreads();
        if (w < 4) {
            const float* aqb = aq + b * D2;
            const float* wl  = wt + l;
            #pragma unroll 16
            for (int d = 320; d < D2; ++d)
                s = fmaf(aqb[d], wl[d * 32], s);
            g_q[b * D2 + e0 + l] = s;
        }
        __threadfence();
        __syncthreads();
        if (tid == 0) atomicAdd(&g_qdone, 1u);
    } else {
        // =================== S part ===================
        __shared__ float sc[Kk];
        float* q_s = dynm;             // [640]
        float* at  = dynm + D2;        // [64][652]

        const int b = blockIdx.x - 40;

        // prefetch a_s_r[b] (10240 f4, 40/thread) — overlaps with Q blocks
        const float* abase = a_s_r + (size_t)b * Kk * D2;
        const uint32_t at_s = smem_u32(at);
        #pragma unroll
        for (int r = 0; r < 40; ++r) {
            const int j   = tid + 256 * r;
            const int row = j / 160;
            const int col = j % 160;
            cpa16(at_s + (uint32_t)(row * SROW2 * 4 + col * 16),
                  abase + row * D2 + col * 4);
        }
        CPA_COMMIT();

        // spin until all 40 Q blocks published g_q
        if (tid == 0) {
            unsigned v;
            do {
                asm volatile("ld.acquire.gpu.global.u32 %0, [%1];"
                             : "=r"(v) : "l"(&g_qdone));
                if (v < 40u) __nanosleep(64);
            } while (v < 40u);
        }
        __syncthreads();
        __threadfence();   // reader-side fence: order g_q reads after flag

        // stage q row into smem (L2-hot after Q phase)
        if (tid < 160) {
            float4 v = *(const float4*)(g_q + b * D2 + tid * 4);
            *(float4*)(q_s + tid * 4) = v;
        }
        CPA_WAIT(0);
        __syncthreads();

        const int k   = tid >> 2;
        const int sub = tid & 3;
        {
            const float* arow = at + k * SROW2 + sub;
            const float* qrow = q_s + sub;
            float s = 0.f;
            #pragma unroll 16
            for (int i = 0; i < 160; ++i)
                s = fmaf(qrow[4 * i], arow[4 * i], s);
            s += __shfl_xor_sync(0xFFFFFFFFu, s, 1);
            s += __shfl_xor_sync(0xFFFFFFFFu, s, 2);
            if (sub == 0) sc[k] = xla_tanhf(s);
        }
        __syncthreads();

        if (tid < 32) {
            const int lane = tid;
            // key = ord(score) << 7 | (127 - k): max key == max score, min idx
            unsigned long long k0 =
                ((unsigned long long)ord_f32(sc[lane]) << 7) | (unsigned)(127 - lane);
            unsigned long long k1 =
                ((unsigned long long)ord_f32(sc[lane + 32]) << 7) | (unsigned)(127 - (lane + 32));

            #pragma unroll
            for (int t = 0; t < TOPK; ++t) {
                unsigned long long m = (k0 > k1) ? k0 : k1;
                #pragma unroll
                for (int o = 16; o > 0; o >>= 1) {
                    unsigned long long other = __shfl_xor_sync(0xFFFFFFFFu, m, o);
                    if (other > m) m = other;
                }
                const int bk = 127 - (int)(m & 127u);
                if (lane == 0) {
                    out[OFF_SCORES  + b * TOPK + t] = sc[bk];
                    out[OFF_RATINGS + b * TOPK + t] = (float)ratings[b * Kk + bk];
                    out[OFF_IDX     + b * TOPK + t] = (float)bk;
                    g_topk_idx[b * TOPK + t] = bk;
                }
                if (bk == lane)      k0 = 0ull;
                if (bk == lane + 32) k1 = 0ull;
            }
        }

        // self-reset the flags for the next (graph-replayed) invocation
        __syncthreads();
        if (tid == 0) {
            unsigned r = atomicAdd(&g_sdone, 1u);
            if (r == 7u) {                 // last score block: all 8 passed
                atomicExch(&g_sdone, 0u);
                atomicExch(&g_qdone, 0u);
            }
        }
    }
}

// ---------------------------------------------------------------------------
// Kernel G: gather. Blocks [0, 2560): h_r copy, 32KB chunks, 8 independent
// f4 ld/st per thread (MLP 8, streaming hints). Blocks [2560, 2688):
// grid-stride over the small segments.
// ---------------------------------------------------------------------------
__global__ __launch_bounds__(256) void gather_kernel(
    const float4* __restrict__ s_r,
    const float4* __restrict__ h_r,
    const float4* __restrict__ r_a,
    const float4* __restrict__ r_o,
    const float4* __restrict__ mask,
    const int4*   __restrict__ rb,
    const float4* __restrict__ rm,
    const int4*   __restrict__ re,
    float4* __restrict__ out4)
{
    __shared__ int idx_s[Bq * TOPK];
    if (threadIdx.x < Bq * TOPK) idx_s[threadIdx.x] = g_topk_idx[threadIdx.x];
    __syncthreads();

    if (blockIdx.x < HR_BLOCKS) {
        const unsigned row   = blockIdx.x >> 5;          // 0..79
        const unsigned chunk = blockIdx.x & 31u;         // 0..31, 2048 f4 each
        const unsigned b     = row / TOPK;
        const unsigned k     = (unsigned)idx_s[row];
        const float4* src = h_r + (b * Kk + k) * 65536u + chunk * 2048u + threadIdx.x;
        float4*       dst = out4 + V4_HR + row * 65536u + chunk * 2048u + threadIdx.x;
        float4 v[8];
        #pragma unroll
        for (int i = 0; i < 8; ++i) v[i] = __ldcs(src + 256 * i);
        #pragma unroll
        for (int i = 0; i < 8; ++i) __stcs(dst + 256 * i, v[i]);
        return;
    }

    const unsigned stride = SM_BLOCKS * 256u;
    for (unsigned g = (blockIdx.x - HR_BLOCKS) * 256u + threadIdx.x;
         g < SM_TOTAL; g += stride) {
        if (g < SM_SR_END) {
            const unsigned row = g >> 9;
            const unsigned iv  = g & 511u;
            const unsigned b   = row / TOPK;
            const unsigned k   = (unsigned)idx_s[row];
            out4[V4_SR + g] = s_r[(b * Kk + k) * 512u + iv];
        } else if (g < SM_RA_END) {
            const unsigned local = g - SM_SR_END;
            const unsigned row = local >> 7;
            const unsigned iv  = local & 127u;
            const unsigned b   = row / TOPK;
            const unsigned k   = (unsigned)idx_s[row];
            out4[V4_RA + local] = r_a[(b * Kk + k) * 128u + iv];
        } else if (g < SM_RO_END) {
            const unsigned local = g - SM_RA_END;
            const unsigned row = local >> 7;
            const unsigned iv  = local & 127u;
            const unsigned b   = row / TOPK;
            const unsigned k   = (unsigned)idx_s[row];
            out4[V4_RO + local] = r_o[(b * Kk + k) * 128u + iv];
        } else if (g < SM_MK_END) {
            const unsigned local = g - SM_RO_END;   // == row
            const unsigned b = local / TOPK;
            const unsigned k = (unsigned)idx_s[local];
            out4[V4_MASK + local] = mask[b * Kk + k];
        } else if (g < SM_RB_END) {
            const unsigned local = g - SM_MK_END;
            const unsigned row = local >> 5;
            const unsigned iv  = local & 31u;
            const unsigned b   = row / TOPK;
            const unsigned k   = (unsigned)idx_s[row];
            const int4 v = rb[(b * Kk + k) * 32u + iv];
            out4[V4_RB + local] = make_float4((float)v.x, (float)v.y, (float)v.z, (float)v.w);
        } else if (g < SM_RM_END) {
            const unsigned local = g - SM_RB_END;
            const unsigned row = local >> 5;
            const unsigned iv  = local & 31u;
            const unsigned b   = row / TOPK;
            const unsigned k   = (unsigned)idx_s[row];
            out4[V4_RM + local] = rm[(b * Kk + k) * 32u + iv];
        } else {
            const unsigned local = g - SM_RM_END;
            const unsigned row = local >> 5;
            const unsigned iv  = local & 31u;
            const unsigned b   = row / TOPK;
            const unsigned k   = (unsigned)idx_s[row];
            const int4 v = re[(b * Kk + k) * 32u + iv];
            out4[V4_RE + local] = make_float4((float)v.x, (float)v.y, (float)v.z, (float)v.w);
        }
    }
}

// ---------------------------------------------------------------------------
extern "C" void kernel_launch(void* const* d_in, const int* in_sizes, int n_in,
                              void* d_out, int out_size)
{
    const float* a_s_q   = (const float*)d_in[0];
    const float* a_s_r   = (const float*)d_in[1];
    const float* W       = (const float*)d_in[2];
    const float* s_r     = (const float*)d_in[3];
    const float* h_r     = (const float*)d_in[4];
    const float* r_a     = (const float*)d_in[5];
    const float* r_o     = (const float*)d_in[6];
    const float* mask    = (const float*)d_in[7];
    const int*   rb      = (const int*)d_in[8];
    const float* rm      = (const float*)d_in[9];
    const int*   ratings = (const int*)d_in[10];
    const int*   re      = (const int*)d_in[11];
    float* out = (float*)d_out;

    // opt-in to >48KB dynamic smem (host-side attribute; idempotent)
    static int attr_done = 0;
    if (!attr_done) {
        cudaFuncSetAttribute(qs_kernel,
            cudaFuncAttributeMaxDynamicSharedMemorySize, QS_SMEM);
        attr_done = 1;
    }

    qs_kernel<<<48, 256, QS_SMEM>>>(a_s_q, W, a_s_r, ratings, out);
    gather_kernel<<<HR_BLOCKS + SM_BLOCKS, 256>>>(
        (const float4*)s_r, (const float4*)h_r, (const float4*)r_a,
        (const float4*)r_o, (const float4*)mask, (const int4*)rb,
        (const float4*)rm, (const int4*)re, (float4*)out);
}